// round 14
// baseline (speedup 1.0000x reference)
#include <cuda_runtime.h>
#include <cuda_fp16.h>
#include <cstdint>
#include <math.h>

// Problem constants: B=4, S=2048, H=D=2048, fp32 I/O.
#define BATCH 4
#define SEQ   2048
#define HID   2048
#define MROWS (BATCH * SEQ)                 // 8192
#define MELEM ((size_t)MROWS * HID)         // 16,777,216
#define WELEM ((size_t)HID * HID)           // 4,194,304

// Segmented scan config
#define NSEG  32
#define SEG   (SEQ / NSEG)                  // 64
#define NCH   (BATCH * HID)                 // 8192

// ---------------------------------------------------------------------------
// Scratch (device globals; allocation is forbidden)
// ---------------------------------------------------------------------------
__device__ float g_K[MELEM];
__device__ float g_V[MELEM];
__device__ __half g_Rh[MELEM];        // sigmoid(r) (fp16)
__device__ __half g_X[3 * MELEM];     // xk/xv/xr (fp16)
__device__ __half g_P[MELEM];         // r*wkv (fp16)
__device__ __half g_W[4 * WELEM];     // Wk,Wv,Wr,Wo (fp16)
__device__ float g_sn[NCH * NSEG], g_sd[NCH * NSEG], g_sm[NCH * NSEG];
__device__ float g_pn[NCH * NSEG], g_pd[NCH * NSEG], g_pm[NCH * NSEG];

// ---------------------------------------------------------------------------
// Helpers
// ---------------------------------------------------------------------------
__device__ __forceinline__ uint32_t smem_to_u32(const void* p) {
    uint32_t a;
    asm("{ .reg .u64 t; cvta.to.shared.u64 t, %1; cvt.u32.u64 %0, t; }"
        : "=r"(a) : "l"(p));
    return a;
}
__device__ __forceinline__ void cp16(uint32_t dst, const void* src) {
    uint64_t g = (uint64_t)__cvta_generic_to_global((void*)src);
    asm volatile("cp.async.cg.shared.global [%0], [%1], 16;" :: "r"(dst), "l"(g));
}
__device__ __forceinline__ void ldsm_x4(uint32_t addr, uint32_t* r) {
    asm volatile("ldmatrix.sync.aligned.m8n8.x4.shared.b16 {%0,%1,%2,%3}, [%4];"
                 : "=r"(r[0]), "=r"(r[1]), "=r"(r[2]), "=r"(r[3]) : "r"(addr));
}
__device__ __forceinline__ void mma_f16(float* d, const uint32_t* a, const uint32_t* b) {
    asm volatile(
        "mma.sync.aligned.m16n8k16.row.col.f32.f16.f16.f32 "
        "{%0,%1,%2,%3}, {%4,%5,%6,%7}, {%8,%9}, {%0,%1,%2,%3};"
        : "+f"(d[0]), "+f"(d[1]), "+f"(d[2]), "+f"(d[3])
        : "r"(a[0]), "r"(a[1]), "r"(a[2]), "r"(a[3]), "r"(b[0]), "r"(b[1]));
}

// SMEM tile: rows x 64 fp16 (128B rows). 16B chunk c (0..7) XOR-swizzled
// by (row & 7): conflict-free for cp.async stores and all ldmatrix phases.
__device__ __forceinline__ uint32_t swz64(uint32_t row, uint32_t c) {
    return row * 128 + ((c ^ (row & 7)) << 4);
}

// ---------------------------------------------------------------------------
// Persistent GEMM: C[m,n] = sum_k A[m,k]*B[n,k]; fp16 operands, fp32 acc.
// CTA tile 256x128, BK=64, 16 warps (64x32 warp tiles), 512 threads,
// 4-stage cp.async pipeline (48KB/stage, 192KB smem), 1 CTA/SM.
// Each CTA walks a round-robin tile list; the (tile x chunk) pipeline is
// flat, so stages for tile t+1 stream in while tile t's epilogue stores.
// kind 0: kvr (T=1536 tiles; z = tile/512 selects k/v/r; r -> sigmoid fp16)
// kind 1: o   (T=512 tiles; fp32 store to out)
// ---------------------------------------------------------------------------
#define STAGE_BYTES 49152            // A 32KB + B 16KB
#define GEMM_SMEM (4 * STAGE_BYTES)  // 192KB (dynamic, opt-in)
#define NIT 32                       // 2048 / 64

__device__ __forceinline__ void load_stage(uint32_t sbase, int cn,
                                           const __half* __restrict__ Ap,
                                           const __half* __restrict__ Bp,
                                           int m0, int n0, int tid)
{
    const int kcol = cn * 64;
#pragma unroll
    for (int i = 0; i < 4; i++) {                    // A: 256 rows x 8 chunks
        const int ch = tid + i * 512;                // 0..2047
        const int row = ch >> 3, c = ch & 7;
        cp16(sbase + swz64(row, c), Ap + (size_t)(m0 + row) * HID + kcol + c * 8);
    }
#pragma unroll
    for (int i = 0; i < 2; i++) {                    // B: 128 rows x 8 chunks
        const int ch = tid + i * 512;                // 0..1023
        const int row = ch >> 3, c = ch & 7;
        cp16(sbase + 32768 + swz64(row, c), Bp + (size_t)(n0 + row) * HID + kcol + c * 8);
    }
    asm volatile("cp.async.commit_group;" ::: "memory");
}

// Issue the load for flat task s (tile = bid + (s/NIT)*G, chunk = s%NIT).
__device__ __forceinline__ void load_task(int kind, int s, int bid, int G,
                                          uint32_t sb, int tid)
{
    const int tl = bid + (s >> 5) * G;       // global tile id
    const int chunk = s & (NIT - 1);
    const int z = (kind == 0) ? (tl >> 9) : 3;
    const int tt = tl & 511;
    const int m0 = (tt >> 4) << 8;           // (tt/16)*256
    const int n0 = (tt & 15) << 7;           // (tt%16)*128
    const __half* A = (kind == 0) ? (g_X + (size_t)z * MELEM) : g_P;
    const __half* B = g_W + (size_t)z * WELEM;
    load_stage(sb + (s & 3) * STAGE_BYTES, chunk, A, B, m0, n0, tid);
}

__device__ void gemm_persist(int kind, float* __restrict__ Cout)
{
    extern __shared__ char smem[];
    const uint32_t sb = smem_to_u32(smem);
    const int tid = threadIdx.x;
    const int lane = tid & 31;
    const int wid = tid >> 5;
    const int wm = (wid & 3) * 64;             // warp M offset (4 warps in M)
    const int wn = (wid >> 2) * 32;            // warp N offset (4 warps in N)
    const int bid = blockIdx.x;
    const int G = gridDim.x;

    const int T = (kind == 0) ? 1536 : 512;
    if (bid >= T) return;
    const int nt = (T - 1 - bid) / G + 1;      // my tile count
    const int total = nt * NIT;

    float acc[4][4][4];
#pragma unroll
    for (int i = 0; i < 4; i++)
#pragma unroll
        for (int j = 0; j < 4; j++)
#pragma unroll
            for (int q = 0; q < 4; q++) acc[i][j][q] = 0.f;

    // Per-lane LDSM row/chunk components
    const int a_row = (lane & 15);
    const int a_kc  = (lane >> 4);             // 16B half of 32B k-slice
    const int b_row = ((lane >> 4) << 3) + (lane & 7);
    const int b_kc  = ((lane >> 3) & 1);

    // prologue: tasks 0,1,2
    load_task(kind, 0, bid, G, sb, tid);
    load_task(kind, 1, bid, G, sb, tid);
    load_task(kind, 2, bid, G, sb, tid);

    for (int s = 0; s < total; ++s) {
        if (s < total - 2)       asm volatile("cp.async.wait_group 2;" ::: "memory");
        else if (s == total - 2) asm volatile("cp.async.wait_group 1;" ::: "memory");
        else                     asm volatile("cp.async.wait_group 0;" ::: "memory");
        __syncthreads();

        if (s + 3 < total)
            load_task(kind, s + 3, bid, G, sb, tid);

        const uint32_t sA = sb + (s & 3) * STAGE_BYTES;
        const uint32_t sB = sA + 32768;

#pragma unroll
        for (int kf = 0; kf < 4; kf++) {       // four k16 slices per BK=64
            uint32_t a[4][4], b[2][4];
#pragma unroll
            for (int mt = 0; mt < 4; mt++)
                ldsm_x4(sA + swz64(wm + mt * 16 + a_row, kf * 2 + a_kc), a[mt]);
#pragma unroll
            for (int np = 0; np < 2; np++)
                ldsm_x4(sB + swz64(wn + np * 16 + b_row, kf * 2 + b_kc), b[np]);
#pragma unroll
            for (int mt = 0; mt < 4; mt++)
#pragma unroll
                for (int nf = 0; nf < 4; nf++)
                    mma_f16(acc[mt][nf], a[mt], &b[nf >> 1][(nf & 1) * 2]);
        }

        if ((s & (NIT - 1)) == NIT - 1) {
            // epilogue for the tile just finished (loads for next tile keep flowing)
            const int tl = bid + (s >> 5) * G;
            const int z = (kind == 0) ? (tl >> 9) : 3;
            const int tt = tl & 511;
            const int m0 = (tt >> 4) << 8;
            const int n0 = (tt & 15) << 7;
            float* C = (kind == 1) ? Cout : ((z == 0) ? g_K : g_V);
            const int mode = (kind == 0 && z == 2) ? 1 : 0;

#pragma unroll
            for (int mt = 0; mt < 4; mt++) {
                const int r0 = m0 + wm + mt * 16 + (lane >> 2);
#pragma unroll
                for (int nf = 0; nf < 4; nf++) {
                    const int col = n0 + wn + nf * 8 + 2 * (lane & 3);
                    if (mode == 1) {
                        float s0 = 1.f / (1.f + __expf(-acc[mt][nf][0]));
                        float s1 = 1.f / (1.f + __expf(-acc[mt][nf][1]));
                        float s2 = 1.f / (1.f + __expf(-acc[mt][nf][2]));
                        float s3 = 1.f / (1.f + __expf(-acc[mt][nf][3]));
                        *reinterpret_cast<__half2*>(g_Rh + (size_t)r0 * HID + col) =
                            __floats2half2_rn(s0, s1);
                        *reinterpret_cast<__half2*>(g_Rh + (size_t)(r0 + 8) * HID + col) =
                            __floats2half2_rn(s2, s3);
                    } else {
                        *reinterpret_cast<float2*>(C + (size_t)r0 * HID + col) =
                            make_float2(acc[mt][nf][0], acc[mt][nf][1]);
                        *reinterpret_cast<float2*>(C + (size_t)(r0 + 8) * HID + col) =
                            make_float2(acc[mt][nf][2], acc[mt][nf][3]);
                    }
                    acc[mt][nf][0] = 0.f; acc[mt][nf][1] = 0.f;
                    acc[mt][nf][2] = 0.f; acc[mt][nf][3] = 0.f;
                }
            }
        }
    }
}

__global__ __launch_bounds__(512, 1)
void gemm_kvr() { gemm_persist(0, nullptr); }

__global__ __launch_bounds__(512, 1)
void gemm_o(float* __restrict__ out) { gemm_persist(1, out); }

// ---------------------------------------------------------------------------
// Prep: fp16 conversions
// ---------------------------------------------------------------------------
__device__ __forceinline__ void h4_store(float a, float b, float c, float d, __half* p)
{
    union { __half v[4]; uint2 u; } H;
    H.v[0] = __float2half_rn(a);
    H.v[1] = __float2half_rn(b);
    H.v[2] = __float2half_rn(c);
    H.v[3] = __float2half_rn(d);
    *reinterpret_cast<uint2*>(p) = H.u;
}

__global__ __launch_bounds__(256)
void prep_w(const float* __restrict__ Wk, const float* __restrict__ Wv,
            const float* __restrict__ Wr, const float* __restrict__ Wo)
{
    const int y = blockIdx.y;
    const float* W = (y == 0) ? Wk : (y == 1) ? Wv : (y == 2) ? Wr : Wo;
    const size_t base = (size_t)y * WELEM;
    const size_t i4 = ((size_t)blockIdx.x * 256 + threadIdx.x) * 4;
    float4 w = *reinterpret_cast<const float4*>(W + i4);
    h4_store(w.x, w.y, w.z, w.w, g_W + base + i4);
}

__global__ __launch_bounds__(256)
void prep_act(const float* __restrict__ hidden, const float* __restrict__ mk,
              const float* __restrict__ mv, const float* __restrict__ mr)
{
    const size_t i4 = ((size_t)blockIdx.x * 256 + threadIdx.x) * 4;
    const int h = (int)(i4 & (HID - 1));
    const int s = (int)((i4 >> 11) & (SEQ - 1));
    const float4 cur = *reinterpret_cast<const float4*>(hidden + i4);
    float4 prv = make_float4(0.f, 0.f, 0.f, 0.f);
    if (s != 0) prv = *reinterpret_cast<const float4*>(hidden + i4 - HID);

    const float4 tk = *reinterpret_cast<const float4*>(mk + h);
    const float4 tv = *reinterpret_cast<const float4*>(mv + h);
    const float4 tr = *reinterpret_cast<const float4*>(mr + h);

    h4_store(fmaf(tk.x, cur.x - prv.x, prv.x), fmaf(tk.y, cur.y - prv.y, prv.y),
             fmaf(tk.z, cur.z - prv.z, prv.z), fmaf(tk.w, cur.w - prv.w, prv.w),
             g_X + i4);
    h4_store(fmaf(tv.x, cur.x - prv.x, prv.x), fmaf(tv.y, cur.y - prv.y, prv.y),
             fmaf(tv.z, cur.z - prv.z, prv.z), fmaf(tv.w, cur.w - prv.w, prv.w),
             g_X + MELEM + i4);
    h4_store(fmaf(tr.x, cur.x - prv.x, prv.x), fmaf(tr.y, cur.y - prv.y, prv.y),
             fmaf(tr.z, cur.z - prv.z, prv.z), fmaf(tr.w, cur.w - prv.w, prv.w),
             g_X + 2 * MELEM + i4);
}

// ---------------------------------------------------------------------------
// WKV segmented scan (exp-stabilized linear recurrence -> associative)
// ---------------------------------------------------------------------------
__global__ void scan_pass1(const float* __restrict__ td)
{
    const int tid = blockIdx.x * blockDim.x + threadIdx.x;  // < NCH*NSEG
    const int d   = tid & (HID - 1);
    const int bs  = tid >> 11;
    const int seg = bs & (NSEG - 1);
    const int b   = bs >> 5;

    const float w = -__expf(td[d]);
    const size_t base = (size_t)(b * SEQ + seg * SEG) * HID + d;

    float num = 0.f, den = 0.f, mx = -1e38f;
#pragma unroll 4
    for (int i = 0; i < SEG; i++) {
        const size_t off = base + (size_t)i * HID;
        const float k = g_K[off];
        const float v = g_V[off];
        const float mn = fmaxf(mx + w, k);
        const float e1 = __expf(mx + w - mn);
        const float e2 = __expf(k - mn);
        num = e1 * num + e2 * v;
        den = e1 * den + e2;
        mx  = mn;
    }
    g_sn[tid] = num; g_sd[tid] = den; g_sm[tid] = mx;
}

__global__ void scan_mid(const float* __restrict__ td)
{
    const int tid = blockIdx.x * blockDim.x + threadIdx.x;  // < NCH
    const int d = tid & (HID - 1);
    const int b = tid >> 11;

    const float w = -__expf(td[d]);
    const float shift = w * (float)SEG;

    float N = 0.f, Dn = 0.f, M = -1e38f;
#pragma unroll
    for (int seg = 0; seg < NSEG; seg++) {
        const int idx = ((b * NSEG + seg) << 11) + d;
        g_pn[idx] = N; g_pd[idx] = Dn; g_pm[idx] = M;
        const float sn = g_sn[idx], sd = g_sd[idx], sm = g_sm[idx];
        const float mf = fmaxf(M + shift, sm);
        const float ea = __expf(M + shift - mf);
        const float eb = __expf(sm - mf);
        N  = ea * N  + eb * sn;
        Dn = ea * Dn + eb * sd;
        M  = mf;
    }
}

__global__ void scan_pass3(const float* __restrict__ td,
                           const float* __restrict__ tfv)
{
    const int tid = blockIdx.x * blockDim.x + threadIdx.x;  // < NCH*NSEG
    const int d   = tid & (HID - 1);
    const int bs  = tid >> 11;
    const int seg = bs & (NSEG - 1);
    const int b   = bs >> 5;

    const float w  = -__expf(td[d]);
    const float tf = tfv[d];
    float num = g_pn[tid], den = g_pd[tid], mx = g_pm[tid];

    const size_t base = (size_t)(b * SEQ + seg * SEG) * HID + d;
#pragma unroll 4
    for (int i = 0; i < SEG; i++) {
        const size_t off = base + (size_t)i * HID;
        const float k = g_K[off];
        const float v = g_V[off];

        const float mo  = fmaxf(mx, k + tf);
        const float o1  = __expf(mx - mo);
        const float o2  = __expf(k + tf - mo);
        const float out = (o1 * num + o2 * v) / (o1 * den + o2);

        const float mn = fmaxf(mx + w, k);
        const float e1 = __expf(mx + w - mn);
        const float e2 = __expf(k - mn);
        num = e1 * num + e2 * v;
        den = e1 * den + e2;
        mx  = mn;

        g_P[off] = __float2half_rn(__half2float(g_Rh[off]) * out);  // r * wkv
    }
}

// ---------------------------------------------------------------------------
// Launch. Input order: hidden, time_decay, time_first, time_mix_key,
// time_mix_value, time_mix_receptance, Wk, Wv, Wr, Wo.
// ---------------------------------------------------------------------------
extern "C" void kernel_launch(void* const* d_in, const int* in_sizes, int n_in,
                              void* d_out, int out_size)
{
    const float* hidden = (const float*)d_in[0];
    const float* td     = (const float*)d_in[1];
    const float* tf     = (const float*)d_in[2];
    const float* mk     = (const float*)d_in[3];
    const float* mv     = (const float*)d_in[4];
    const float* mr     = (const float*)d_in[5];
    const float* Wk     = (const float*)d_in[6];
    const float* Wv     = (const float*)d_in[7];
    const float* Wr     = (const float*)d_in[8];
    const float* Wo     = (const float*)d_in[9];
    float* out          = (float*)d_out;

    // Host-side, idempotent, capture-safe (queries/attributes only).
    cudaFuncSetAttribute(gemm_kvr, cudaFuncAttributeMaxDynamicSharedMemorySize, GEMM_SMEM);
    cudaFuncSetAttribute(gemm_o,   cudaFuncAttributeMaxDynamicSharedMemorySize, GEMM_SMEM);
    int nsm = 148;
    cudaDeviceGetAttribute(&nsm, cudaDevAttrMultiProcessorCount, 0);

    prep_w  <<<dim3(4096, 4), 256>>>(Wk, Wv, Wr, Wo);
    prep_act<<<16384, 256>>>(hidden, mk, mv, mr);

    gemm_kvr<<<nsm, 512, GEMM_SMEM>>>();

    scan_pass1<<<(NCH * NSEG) / 256, 256>>>(td);
    scan_mid  <<<NCH / 256, 256>>>(td);
    scan_pass3<<<(NCH * NSEG) / 256, 256>>>(td, tf);

    gemm_o<<<nsm, 512, GEMM_SMEM>>>(out);
}